// round 1
// baseline (speedup 1.0000x reference)
#include <cuda_runtime.h>
#include <cuda_bf16.h>

// CALayer (squeeze-excitation): x:[16,256,128,128] f32
//   mean over HW -> [16,256]; h = relu(w1@m + b1) [16,16]; y = sigmoid(w2@h + b2) [16,256]
//   out = x * y[b,c]
// HBM-bound: 2 reads + 1 write of 268MB. Three kernels, all graph-capturable.

#define BATCH 16
#define CHAN 256
#define CR 16
#define HW 16384          // 128*128
#define NPLANES (BATCH*CHAN)   // 4096

__device__ float g_mean[NPLANES];
__device__ float g_scale[NPLANES];

// ---------------- Kernel 1: per-plane mean ----------------
// One block per plane. 256 threads, each loads 16 float4 (4096 float4/plane).
__global__ __launch_bounds__(256) void plane_mean_kernel(const float* __restrict__ x) {
    const int p = blockIdx.x;
    const float4* __restrict__ xp = reinterpret_cast<const float4*>(x + (size_t)p * HW);
    float s = 0.f;
    #pragma unroll
    for (int i = 0; i < 16; i++) {
        float4 v = __ldg(&xp[threadIdx.x + i * 256]);
        s += (v.x + v.y) + (v.z + v.w);
    }
    // warp reduce
    #pragma unroll
    for (int o = 16; o > 0; o >>= 1) s += __shfl_xor_sync(0xFFFFFFFF, s, o);
    __shared__ float sh[8];
    const int wid = threadIdx.x >> 5;
    if ((threadIdx.x & 31) == 0) sh[wid] = s;
    __syncthreads();
    if (threadIdx.x == 0) {
        float t = 0.f;
        #pragma unroll
        for (int w = 0; w < 8; w++) t += sh[w];
        g_mean[p] = t * (1.0f / HW);
    }
}

// ---------------- Kernel 2: SE MLP ----------------
// One block per batch. 256 threads.
__global__ __launch_bounds__(256) void se_mlp_kernel(const float* __restrict__ w1,
                                                     const float* __restrict__ b1,
                                                     const float* __restrict__ w2,
                                                     const float* __restrict__ b2) {
    const int b = blockIdx.x;
    const int tid = threadIdx.x;
    __shared__ float smean[CHAN];
    __shared__ float sh[CR];
    smean[tid] = g_mean[b * CHAN + tid];
    __syncthreads();

    // hidden: 16 dot products of length 256. 8 warps -> 2 r's per warp.
    const int wid = tid >> 5;
    const int lane = tid & 31;
    #pragma unroll
    for (int k = 0; k < 2; k++) {
        const int r = wid * 2 + k;
        float acc = 0.f;
        #pragma unroll
        for (int c = lane; c < CHAN; c += 32)
            acc += w1[r * CHAN + c] * smean[c];
        #pragma unroll
        for (int o = 16; o > 0; o >>= 1) acc += __shfl_xor_sync(0xFFFFFFFF, acc, o);
        if (lane == 0) sh[r] = fmaxf(acc + b1[r], 0.f);
    }
    __syncthreads();

    // output: each thread handles one channel c
    float acc = b2[tid];
    #pragma unroll
    for (int r = 0; r < CR; r++)
        acc += w2[tid * CR + r] * sh[r];
    g_scale[b * CHAN + tid] = 1.0f / (1.0f + __expf(-acc));
}

// ---------------- Kernel 3: broadcast scale ----------------
// One block per plane; scale uniform across the block.
__global__ __launch_bounds__(256) void scale_kernel(const float* __restrict__ x,
                                                    float* __restrict__ out) {
    const int p = blockIdx.x;
    const float s = g_scale[p];
    const float4* __restrict__ xp = reinterpret_cast<const float4*>(x + (size_t)p * HW);
    float4* __restrict__ op = reinterpret_cast<float4*>(out + (size_t)p * HW);
    #pragma unroll
    for (int i = 0; i < 16; i++) {
        const int idx = threadIdx.x + i * 256;
        float4 v = __ldg(&xp[idx]);
        v.x *= s; v.y *= s; v.z *= s; v.w *= s;
        op[idx] = v;
    }
}

extern "C" void kernel_launch(void* const* d_in, const int* in_sizes, int n_in,
                              void* d_out, int out_size) {
    const float* x  = (const float*)d_in[0];
    const float* w1 = (const float*)d_in[1];
    const float* b1 = (const float*)d_in[2];
    const float* w2 = (const float*)d_in[3];
    const float* b2 = (const float*)d_in[4];
    float* out = (float*)d_out;

    plane_mean_kernel<<<NPLANES, 256>>>(x);
    se_mlp_kernel<<<BATCH, 256>>>(w1, b1, w2, b2);
    scale_kernel<<<NPLANES, 256>>>(x, out);
}

// round 2
// speedup vs baseline: 1.0188x; 1.0188x over previous
#include <cuda_runtime.h>
#include <cuda_bf16.h>

// CALayer (squeeze-excitation): x:[16,256,128,128] f32
//   mean over HW -> [16,256]; h = relu(w1@m + b1); y = sigmoid(w2@h + b2)
//   out = x * y[b,c]
// HBM-bound. R1: exploit L2 residency of the tail of x between the mean pass
// and the scale pass: scale pass walks planes in REVERSE order and uses
// streaming loads/stores so its own traffic doesn't evict the reusable tail.

#define BATCH 16
#define CHAN 256
#define CR 16
#define HW 16384               // 128*128
#define NPLANES (BATCH*CHAN)   // 4096

__device__ float g_mean[NPLANES];
__device__ float g_scale[NPLANES];

// ---------------- Kernel 1: per-plane mean ----------------
__global__ __launch_bounds__(256) void plane_mean_kernel(const float* __restrict__ x) {
    const int p = blockIdx.x;
    const float4* __restrict__ xp = reinterpret_cast<const float4*>(x + (size_t)p * HW);
    float s = 0.f;
    #pragma unroll
    for (int i = 0; i < 16; i++) {
        float4 v = __ldg(&xp[threadIdx.x + i * 256]);
        s += (v.x + v.y) + (v.z + v.w);
    }
    #pragma unroll
    for (int o = 16; o > 0; o >>= 1) s += __shfl_xor_sync(0xFFFFFFFF, s, o);
    __shared__ float sh[8];
    const int wid = threadIdx.x >> 5;
    if ((threadIdx.x & 31) == 0) sh[wid] = s;
    __syncthreads();
    if (threadIdx.x == 0) {
        float t = 0.f;
        #pragma unroll
        for (int w = 0; w < 8; w++) t += sh[w];
        g_mean[p] = t * (1.0f / HW);
    }
}

// ---------------- Kernel 2: SE MLP ----------------
__global__ __launch_bounds__(256) void se_mlp_kernel(const float* __restrict__ w1,
                                                     const float* __restrict__ b1,
                                                     const float* __restrict__ w2,
                                                     const float* __restrict__ b2) {
    const int b = blockIdx.x;
    const int tid = threadIdx.x;
    __shared__ float smean[CHAN];
    __shared__ float sh[CR];
    smean[tid] = g_mean[b * CHAN + tid];
    __syncthreads();

    const int wid = tid >> 5;
    const int lane = tid & 31;
    #pragma unroll
    for (int k = 0; k < 2; k++) {
        const int r = wid * 2 + k;
        float acc = 0.f;
        #pragma unroll
        for (int c = lane; c < CHAN; c += 32)
            acc += w1[r * CHAN + c] * smean[c];
        #pragma unroll
        for (int o = 16; o > 0; o >>= 1) acc += __shfl_xor_sync(0xFFFFFFFF, acc, o);
        if (lane == 0) sh[r] = fmaxf(acc + b1[r], 0.f);
    }
    __syncthreads();

    float acc = b2[tid];
    #pragma unroll
    for (int r = 0; r < CR; r++)
        acc += w2[tid * CR + r] * sh[r];
    g_scale[b * CHAN + tid] = 1.0f / (1.0f + __expf(-acc));
}

// ---------------- Kernel 3: broadcast scale (reverse order, streaming) ----------------
__device__ __forceinline__ float4 ldcs4(const float4* p) {
    float4 v;
    asm volatile("ld.global.cs.v4.f32 {%0,%1,%2,%3}, [%4];"
                 : "=f"(v.x), "=f"(v.y), "=f"(v.z), "=f"(v.w) : "l"(p));
    return v;
}
__device__ __forceinline__ void stcs4(float4* p, float4 v) {
    asm volatile("st.global.cs.v4.f32 [%0], {%1,%2,%3,%4};"
                 :: "l"(p), "f"(v.x), "f"(v.y), "f"(v.z), "f"(v.w) : "memory");
}

__global__ __launch_bounds__(256) void scale_kernel(const float* __restrict__ x,
                                                    float* __restrict__ out) {
    // Reverse plane order: first blocks touch the planes the mean pass read
    // last, which are still resident in L2.
    const int p = (NPLANES - 1) - blockIdx.x;
    const float s = g_scale[p];
    const float4* __restrict__ xp = reinterpret_cast<const float4*>(x + (size_t)p * HW);
    float4* __restrict__ op = reinterpret_cast<float4*>(out + (size_t)p * HW);
    #pragma unroll
    for (int i = 0; i < 16; i++) {
        const int idx = threadIdx.x + i * 256;
        float4 v = ldcs4(&xp[idx]);
        v.x *= s; v.y *= s; v.z *= s; v.w *= s;
        stcs4(&op[idx], v);
    }
}

extern "C" void kernel_launch(void* const* d_in, const int* in_sizes, int n_in,
                              void* d_out, int out_size) {
    const float* x  = (const float*)d_in[0];
    const float* w1 = (const float*)d_in[1];
    const float* b1 = (const float*)d_in[2];
    const float* w2 = (const float*)d_in[3];
    const float* b2 = (const float*)d_in[4];
    float* out = (float*)d_out;

    plane_mean_kernel<<<NPLANES, 256>>>(x);
    se_mlp_kernel<<<BATCH, 256>>>(w1, b1, w2, b2);
    scale_kernel<<<NPLANES, 256>>>(x, out);
}